// round 5
// baseline (speedup 1.0000x reference)
#include <cuda_runtime.h>
#include <cuda_bf16.h>
#include <cstdint>

typedef unsigned long long u64;

// ---------------- packed fp32 helpers (sm_103a f32x2) ----------------
__device__ __forceinline__ u64 dup2(float x) {
    u64 r; asm("mov.b64 %0, {%1, %1};" : "=l"(r) : "f"(x)); return r;
}
__device__ __forceinline__ u64 fma2(u64 a, u64 b, u64 c) {
    u64 d; asm("fma.rn.f32x2 %0, %1, %2, %3;" : "=l"(d) : "l"(a), "l"(b), "l"(c));
    return d;
}
__device__ __forceinline__ void unpack2(float& lo, float& hi, u64 v) {
    asm("mov.b64 {%0, %1}, %2;" : "=f"(lo), "=f"(hi) : "l"(v));
}
__device__ __forceinline__ uint32_t smem_u32(const void* p) {
    uint32_t a;
    asm("{ .reg .u64 t0; cvta.to.shared.u64 t0, %1; cvt.u32.u64 %0, t0; }"
        : "=r"(a) : "l"(p));
    return a;
}
__device__ __forceinline__ void st_cluster_f32(uint32_t saddr, uint32_t rank, float v) {
    uint32_t remote;
    asm("mapa.shared::cluster.u32 %0, %1, %2;" : "=r"(remote) : "r"(saddr), "r"(rank));
    asm volatile("st.shared::cluster.f32 [%0], %1;" :: "r"(remote), "f"(v) : "memory");
}
__device__ __forceinline__ uint32_t ctarank() {
    uint32_t r; asm("mov.u32 %0, %%cluster_ctarank;" : "=r"(r)); return r;
}
__device__ __forceinline__ void cluster_sync_() {
    asm volatile("barrier.cluster.arrive.aligned;" ::: "memory");
    asm volatile("barrier.cluster.wait.aligned;" ::: "memory");
}

// =====================================================================
// Kernel 1: out = inputs @ W_xh + b_h   (M=65536, K=256, N=512)
// 128x128x8 tile, 256 threads, 8x8 microtile, f32x2 accumulation.
// =====================================================================
__global__ void __launch_bounds__(256)
xw_gemm_kernel(const float* __restrict__ A, const float* __restrict__ B,
               const float* __restrict__ bias, float* __restrict__ C) {
    __shared__ __align__(16) float As[8][128];
    __shared__ __align__(16) float Bs[8][128];
    const int tid = threadIdx.x;
    const int bn  = blockIdx.x;        // 0..3
    const int bm  = blockIdx.y;        // 0..511
    const int tx  = tid & 15;          // col group (8 cols)
    const int ty  = tid >> 4;          // row group (8 rows)
    const int arow = tid >> 1, acol = (tid & 1) << 2;
    const int brow = tid >> 5, bcol = (tid & 31) << 2;
    const float* Ab = A + (size_t)bm * 128 * 256;
    const float* Bb = B + bn * 128;

    u64 acc2[8][4];
#pragma unroll
    for (int i = 0; i < 8; i++)
#pragma unroll
        for (int j = 0; j < 4; j++) acc2[i][j] = dup2(0.0f);

    for (int k0 = 0; k0 < 256; k0 += 8) {
        float4 av = *(const float4*)(Ab + (size_t)arow * 256 + k0 + acol);
        As[acol + 0][arow] = av.x;
        As[acol + 1][arow] = av.y;
        As[acol + 2][arow] = av.z;
        As[acol + 3][arow] = av.w;
        *(float4*)&Bs[brow][bcol] =
            *(const float4*)(Bb + (size_t)(k0 + brow) * 512 + bcol);
        __syncthreads();
#pragma unroll
        for (int k = 0; k < 8; k++) {
            float4 a0 = *(const float4*)&As[k][ty * 8];
            float4 a1 = *(const float4*)&As[k][ty * 8 + 4];
            const u64* bp = (const u64*)&Bs[k][tx * 8];
            u64 b2[4];
#pragma unroll
            for (int j = 0; j < 4; j++) b2[j] = bp[j];
            u64 ad[8];
            ad[0] = dup2(a0.x); ad[1] = dup2(a0.y);
            ad[2] = dup2(a0.z); ad[3] = dup2(a0.w);
            ad[4] = dup2(a1.x); ad[5] = dup2(a1.y);
            ad[6] = dup2(a1.z); ad[7] = dup2(a1.w);
#pragma unroll
            for (int i = 0; i < 8; i++)
#pragma unroll
                for (int j = 0; j < 4; j++)
                    acc2[i][j] = fma2(ad[i], b2[j], acc2[i][j]);
        }
        __syncthreads();
    }

    float bi[8];
#pragma unroll
    for (int j = 0; j < 8; j++) bi[j] = bias[bn * 128 + tx * 8 + j];
#pragma unroll
    for (int i = 0; i < 8; i++) {
        size_t row = (size_t)bm * 128 + ty * 8 + i;
        float* cp = C + row * 512 + bn * 128 + tx * 8;
        float v[8];
#pragma unroll
        for (int j = 0; j < 4; j++) unpack2(v[2 * j], v[2 * j + 1], acc2[i][j]);
#pragma unroll
        for (int j = 0; j < 8; j++) v[j] += bi[j];
        *(float4*)(cp + 0) = make_float4(v[0], v[1], v[2], v[3]);
        *(float4*)(cp + 4) = make_float4(v[4], v[5], v[6], v[7]);
    }
}

// =====================================================================
// Kernel 2: recurrence. 16 clusters x 8 CTAs x 256 threads.
// Cluster cl owns batches [cl*4, cl*4+4). CTA rank r owns W_hh columns
// [r*64, r*64+64) resident in SMEM. Full h (512 x 4 batches) replicated
// per CTA, double-buffered; written each step via DSMEM broadcast.
// d_out holds xw on entry per (b,t); overwritten with h_t in place.
// =====================================================================
#define REC_SMEM_BYTES (131072 + 16384 + 8192)

__global__ void __launch_bounds__(256, 1) __cluster_dims__(8, 1, 1)
rnn_rec_kernel(const float* __restrict__ W_hh, float* __restrict__ out) {
    extern __shared__ __align__(16) float smem[];
    float* Ws   = smem;                 // [512][64]
    float* hb   = smem + 32768;         // [2][512][4]
    u64*   red64 = (u64*)(smem + 32768 + 4096);   // [8][2][16][4]

    const int tid = threadIdx.x;
    const uint32_t r  = ctarank();          // 0..7
    const int cl      = blockIdx.x >> 3;    // 0..15
    const int b0      = cl * 4;

    // load W slice: Ws[k][c] = W_hh[k*512 + r*64 + c]
    {
        float4* Ws4 = (float4*)Ws;
        const float4* Wg4 = (const float4*)W_hh;
        for (int i = tid; i < 8192; i += 256) {
            int k = i >> 4, cg = i & 15;
            Ws4[i] = Wg4[(size_t)k * 128 + r * 16 + cg];
        }
    }
    // zero h buffer 0
    for (int i = tid; i < 2048; i += 256) hb[i] = 0.0f;
    __syncthreads();
    cluster_sync_();

    // k-loop mapping
    const int w  = tid >> 5;           // warp 0..7 -> k in [w*64, w*64+64)
    const int ln = tid & 31;
    const int cg = ln & 15;            // 4-col group
    const int p  = ln >> 4;            // batch-pair 0/1
    // reducer mapping
    const int rc = tid >> 2;           // col 0..63
    const int rb = tid & 3;            // batch 0..3
    const float4* Ws4 = (const float4*)Ws;
    const u64* hb64 = (const u64*)hb;
    const float* redf = (const float*)red64;
    const uint32_t hb_s = smem_u32(hb);
    const size_t obase0 = ((size_t)(b0 + rb) * 1024) * 512 + r * 64 + rc;

    int cur = 0;
    for (int t = 0; t < 1024; t++) {
        // prefetch xw (this thread's output element)
        const size_t oidx = obase0 + (size_t)t * 512;
        float xw_v = __ldg(out + oidx);

        // split-K GEMV: partials for 4 cols x 2 batches (packed)
        u64 a0 = dup2(0.0f), a1 = a0, a2 = a0, a3 = a0;
        const int kbeg = w * 64;
        const u64* hrow = hb64 + (size_t)cur * 1024 + p;
#pragma unroll 4
        for (int k = kbeg; k < kbeg + 64; k++) {
            float4 wv = Ws4[k * 16 + cg];
            u64 hp = hrow[k * 2];
            a0 = fma2(dup2(wv.x), hp, a0);
            a1 = fma2(dup2(wv.y), hp, a1);
            a2 = fma2(dup2(wv.z), hp, a2);
            a3 = fma2(dup2(wv.w), hp, a3);
        }
        u64* rp = red64 + w * 128 + p * 64 + cg * 4;
        rp[0] = a0; rp[1] = a1; rp[2] = a2; rp[3] = a3;
        __syncthreads();

        // reduce 8 warp-partials, add xw, tanh
        const int roff = (rb >> 1) * 128 + (rc >> 2) * 8 + (rc & 3) * 2 + (rb & 1);
        float s = xw_v;
#pragma unroll
        for (int ww = 0; ww < 8; ww++) s += redf[ww * 256 + roff];
        float h = tanhf(s);

        // write output
        out[oidx] = h;

        // broadcast h to all 8 cluster CTAs' next buffer
        const int nxt = cur ^ 1;
        const uint32_t soff = hb_s + (uint32_t)(nxt * 2048 + (r * 64 + rc) * 4 + rb) * 4;
#pragma unroll
        for (uint32_t rk = 0; rk < 8; rk++) st_cluster_f32(soff, rk, h);

        cluster_sync_();
        cur = nxt;
    }
}

// =====================================================================
extern "C" void kernel_launch(void* const* d_in, const int* in_sizes, int n_in,
                              void* d_out, int out_size) {
    const float* inputs = (const float*)d_in[0];  // (64,1024,256)
    const float* W_xh   = (const float*)d_in[1];  // (256,512)
    const float* W_hh   = (const float*)d_in[2];  // (512,512)
    const float* b_h    = (const float*)d_in[3];  // (512,)
    float* out = (float*)d_out;                   // (64,1024,512)

    static bool attr_set = false;
    if (!attr_set) {
        cudaFuncSetAttribute(rnn_rec_kernel,
                             cudaFuncAttributeMaxDynamicSharedMemorySize,
                             REC_SMEM_BYTES);
        attr_set = true;
    }

    dim3 g1(4, 512);
    xw_gemm_kernel<<<g1, 256>>>(inputs, W_xh, b_h, out);

    rnn_rec_kernel<<<128, 256, REC_SMEM_BYTES>>>(W_hh, out);
}